// round 4
// baseline (speedup 1.0000x reference)
#include <cuda_runtime.h>

#define TW 64
#define TH 32
#define NT 256
#define S  80   // unified smem row stride (floats)

#define GW 76   /* gray  cols, base ox-6 */
#define GH 44   /* gray  rows, base oy-6 */
#define HBW 72  /* hblur cols, base ox-4 (rows base oy-6) */
#define HBH 44
#define BW 72   /* blur cols, base ox-4 */
#define BH 40   /* blur rows, base oy-4 */
#define MW 70   /* mag  cols, base ox-3 */
#define MH 38   /* mag  rows, base oy-3 */
#define NW 68   /* nms  cols, base ox-2 */
#define NH 36   /* nms  rows, base oy-2 */
#define RW 68   /* colmax cols, base ox-2 */
#define RH 32   /* colmax rows, base oy   */

#define LD2(p)      (*(const float2*)(p))
#define ST2(p, v)   (*(float2*)(p) = (v))

__global__ __launch_bounds__(NT) void canny_edge_kernel(
    const float* __restrict__ x, float* __restrict__ out)
{
    __shared__ __align__(16) float A[GH * S];          // gray -> blur -> nms
    __shared__ __align__(16) float B[GH * S];          // hblur -> mag -> colmax
    __shared__ __align__(4)  unsigned char C[MH * S];  // gradient axis (0..3)

    const int tid = threadIdx.x;
    const int ox = blockIdx.x * TW;
    const int oy = blockIdx.y * TH;
    const int n  = blockIdx.z;

    const float gk0 = 0.054488685f;
    const float gk1 = 0.244201342f;
    const float gk2 = 0.402619947f;
    const float gk[5] = {gk0, gk1, gk2, gk1, gk0};

    const float* c0 = x + ((size_t)n * 3 + 0) * 512 * 512;
    const float* c1 = x + ((size_t)n * 3 + 1) * 512 * 512;
    const float* c2 = x + ((size_t)n * 3 + 2) * 512 * 512;

    const bool interior = (ox >= 6) && (ox + TW + 6 <= 512) &&
                          (oy >= 6) && (oy + TH + 6 <= 512);

    const float t1 = 0.41421356237f;  // tan(22.5 deg)
    const float t2 = 2.41421356237f;  // tan(67.5 deg)

    if (interior) {
        const int tx2 = tid & 31;   // column-pair index
        const int ty8 = tid >> 5;   // 0..7

        // ---- Stage 1: grayscale (channels reversed) ----
        {
            const int gbase = (oy - 6) * 512 + (ox - 6);
            for (int lr = ty8; lr < GH; lr += 8) {
                const int rowg = gbase + lr * 512;
                #pragma unroll 2
                for (int pass = 0; pass < 2; pass++) {
                    if (pass == 1 && tx2 >= (GW / 2 - 32)) break;
                    int p = tx2 + pass * 32;
                    float2 a0 = LD2(c0 + rowg + 2 * p);
                    float2 a1 = LD2(c1 + rowg + 2 * p);
                    float2 a2 = LD2(c2 + rowg + 2 * p);
                    float2 g;
                    g.x = 0.299f * a2.x + 0.587f * a1.x + 0.114f * a0.x;
                    g.y = 0.299f * a2.y + 0.587f * a1.y + 0.114f * a0.y;
                    ST2(&A[lr * S + 2 * p], g);
                }
            }
        }
        __syncthreads();

        // ---- Stage 2: horizontal blur -> B ----
        for (int lr = ty8; lr < HBH; lr += 8) {
            const float* a = &A[lr * S];
            #pragma unroll 2
            for (int pass = 0; pass < 2; pass++) {
                if (pass == 1 && tx2 >= (HBW / 2 - 32)) break;
                int p = tx2 + pass * 32;
                float2 u = LD2(a + 2 * p);
                float2 v = LD2(a + 2 * p + 2);
                float2 w = LD2(a + 2 * p + 4);
                float2 o;
                o.x = gk0 * (u.x + w.x) + gk1 * (u.y + v.y) + gk2 * v.x;
                o.y = gk0 * (u.y + w.y) + gk1 * (v.x + w.x) + gk2 * v.y;
                ST2(&B[lr * S + 2 * p], o);
            }
        }
        __syncthreads();

        // ---- Stage 3: vertical blur -> A (rolling 5-row window) ----
        {
            const int r0 = ty8 * 5;  // 8 chunks x 5 = 40 rows
            #pragma unroll 2
            for (int pass = 0; pass < 2; pass++) {
                if (pass == 1 && tx2 >= (BW / 2 - 32)) break;
                int c = 2 * (tx2 + pass * 32);
                float2 w0 = LD2(&B[(r0 + 0) * S + c]);
                float2 w1 = LD2(&B[(r0 + 1) * S + c]);
                float2 w2 = LD2(&B[(r0 + 2) * S + c]);
                float2 w3 = LD2(&B[(r0 + 3) * S + c]);
                #pragma unroll
                for (int j = 0; j < 5; j++) {
                    float2 w4 = LD2(&B[(r0 + j + 4) * S + c]);
                    float2 o;
                    o.x = gk0 * (w0.x + w4.x) + gk1 * (w1.x + w3.x) + gk2 * w2.x;
                    o.y = gk0 * (w0.y + w4.y) + gk1 * (w1.y + w3.y) + gk2 * w2.y;
                    ST2(&A[(r0 + j) * S + c], o);
                    w0 = w1; w1 = w2; w2 = w3; w3 = w4;
                }
            }
        }
        __syncthreads();

        // ---- Stage 4: Sobel + magnitude -> B (base ox-3), axis -> C ----
        // mag col j taps blur cols j..j+2 (rel base ox-4); rows j..j+2.
        {
            const int r0 = ty8 * 5;
            const int cnt = min(5, MH - r0);  // MH=38: last chunk 3 rows
            #pragma unroll 2
            for (int pass = 0; pass < 2; pass++) {
                if (pass == 1 && tx2 >= 3) break;  // 35 pairs
                int p = tx2 + pass * 32;
                int c = 2 * p;
                float2 a0 = LD2(&A[(r0 + 0) * S + c]);
                float2 b0 = LD2(&A[(r0 + 0) * S + c + 2]);
                float2 a1 = LD2(&A[(r0 + 1) * S + c]);
                float2 b1 = LD2(&A[(r0 + 1) * S + c + 2]);
                for (int j = 0; j < cnt; j++) {
                    float2 a2 = LD2(&A[(r0 + j + 2) * S + c]);
                    float2 b2 = LD2(&A[(r0 + j + 2) * S + c + 2]);
                    // col 2p: l=a.x m=a.y r=b.x
                    float sx0 = 0.125f * (b0.x - a0.x) + 0.25f * (b1.x - a1.x) + 0.125f * (b2.x - a2.x);
                    float sy0 = 0.125f * (a2.x - a0.x) + 0.25f * (a2.y - a0.y) + 0.125f * (b2.x - b0.x);
                    // col 2p+1: l=a.y m=b.x r=b.y
                    float sx1 = 0.125f * (b0.y - a0.y) + 0.25f * (b1.y - a1.y) + 0.125f * (b2.y - a2.y);
                    float sy1 = 0.125f * (a2.y - a0.y) + 0.25f * (b2.x - b0.x) + 0.125f * (b2.y - b0.y);
                    float2 m;
                    m.x = sqrtf(sx0 * sx0 + sy0 * sy0 + 1e-6f);
                    m.y = sqrtf(sx1 * sx1 + sy1 * sy1 + 1e-6f);
                    float adx0 = fabsf(sx0), ady0 = fabsf(sy0);
                    float adx1 = fabsf(sx1), ady1 = fabsf(sy1);
                    int ax0, ax1;
                    if (ady0 <= adx0 * t1)      ax0 = 0;
                    else if (ady0 >= adx0 * t2) ax0 = 2;
                    else                        ax0 = ((sx0 > 0.f) == (sy0 > 0.f)) ? 1 : 3;
                    if (ady1 <= adx1 * t1)      ax1 = 0;
                    else if (ady1 >= adx1 * t2) ax1 = 2;
                    else                        ax1 = ((sx1 > 0.f) == (sy1 > 0.f)) ? 1 : 3;
                    ST2(&B[(r0 + j) * S + c], m);
                    uchar2 axp; axp.x = (unsigned char)ax0; axp.y = (unsigned char)ax1;
                    *(uchar2*)&C[(r0 + j) * S + c] = axp;
                    a0 = a1; b0 = b1;
                    a1 = a2; b1 = b2;
                }
            }
        }
        __syncthreads();

        // ---- Stage 5: NMS -> A (nms (lr,lc) = mag (lr+1, lc+1)) ----
        for (int lr = ty8; lr < NH; lr += 8) {
            #pragma unroll 2
            for (int pass = 0; pass < 2; pass++) {
                if (pass == 1 && tx2 >= 2) break;  // 34 pairs
                int lc = 2 * (tx2 + pass * 32);
                int mi = (lr + 1) * S + lc + 1;
                float m0 = B[mi], m1 = B[mi + 1];
                int ax0 = C[mi], ax1 = C[mi + 1];
                int o0 = (ax0 == 0) ? 1 : ((ax0 == 1) ? S + 1 : ((ax0 == 2) ? S : S - 1));
                int o1 = (ax1 == 0) ? 1 : ((ax1 == 1) ? S + 1 : ((ax1 == 2) ? S : S - 1));
                float p0 = B[mi + o0], q0 = B[mi - o0];
                float p1 = B[mi + 1 + o1], q1 = B[mi + 1 - o1];
                float2 o;
                o.x = (m0 > p0 && m0 > q0) ? m0 : 0.f;
                o.y = (m1 > p1 && m1 > q1) ? m1 : 0.f;
                ST2(&A[lr * S + lc], o);
            }
        }
        __syncthreads();

        // ---- Stage 6: vertical 5-max -> B (rolling) ----
        {
            const int r0 = ty8 * 4;  // 8 chunks x 4 = 32 rows
            #pragma unroll 2
            for (int pass = 0; pass < 2; pass++) {
                if (pass == 1 && tx2 >= 2) break;  // 34 pairs
                int c = 2 * (tx2 + pass * 32);
                float2 w0 = LD2(&A[(r0 + 0) * S + c]);
                float2 w1 = LD2(&A[(r0 + 1) * S + c]);
                float2 w2 = LD2(&A[(r0 + 2) * S + c]);
                float2 w3 = LD2(&A[(r0 + 3) * S + c]);
                #pragma unroll
                for (int j = 0; j < 4; j++) {
                    float2 w4 = LD2(&A[(r0 + j + 4) * S + c]);
                    float2 o;
                    o.x = fmaxf(fmaxf(fmaxf(w0.x, w1.x), fmaxf(w2.x, w3.x)), w4.x);
                    o.y = fmaxf(fmaxf(fmaxf(w0.y, w1.y), fmaxf(w2.y, w3.y)), w4.y);
                    ST2(&B[(r0 + j) * S + c], o);
                    w0 = w1; w1 = w2; w2 = w3; w3 = w4;
                }
            }
        }
        __syncthreads();

        // ---- Stage 7: horizontal 5-max, vectorized store ----
        for (int lr = ty8; lr < TH; lr += 8) {
            int c = 2 * tx2;  // colmax base ox-2; out pair taps cols c..c+5
            float2 a = LD2(&B[lr * S + c]);
            float2 b = LD2(&B[lr * S + c + 2]);
            float2 d = LD2(&B[lr * S + c + 4]);
            float2 o;
            o.x = fmaxf(fmaxf(fmaxf(a.x, a.y), fmaxf(b.x, b.y)), d.x);
            o.y = fmaxf(fmaxf(fmaxf(a.y, b.x), fmaxf(b.y, d.x)), d.y);
            ST2(&out[((size_t)n * 512 + (oy + lr)) * 512 + (ox + c)], o);
        }
    } else {
        // ================= boundary path (reflect/edge handling) =============
        for (int i = tid; i < GH * GW; i += NT) {
            int lr = i / GW, lc = i - lr * GW;
            int gy = oy - 6 + lr, gx = ox - 6 + lc;
            float v = 0.f;
            if ((unsigned)gy < 512u && (unsigned)gx < 512u) {
                int idx = gy * 512 + gx;
                v = 0.299f * c2[idx] + 0.587f * c1[idx] + 0.114f * c0[idx];
            }
            A[lr * S + lc] = v;
        }
        __syncthreads();

        for (int i = tid; i < HBH * HBW; i += NT) {
            int lr = i / HBW, lc = i - lr * HBW;
            int gx = ox - 4 + lc;
            float s = 0.f;
            #pragma unroll
            for (int k = 0; k < 5; k++) {
                int c = gx + k - 2;
                c = (c < 0) ? -c : ((c > 511) ? 1022 - c : c);
                int lcg = c - (ox - 6);
                lcg = min(max(lcg, 0), GW - 1);
                s += gk[k] * A[lr * S + lcg];
            }
            B[lr * S + lc] = s;
        }
        __syncthreads();

        for (int i = tid; i < BH * BW; i += NT) {
            int lr = i / BW, lc = i - lr * BW;
            int gy = oy - 4 + lr;
            float s = 0.f;
            #pragma unroll
            for (int k = 0; k < 5; k++) {
                int r = gy + k - 2;
                r = (r < 0) ? -r : ((r > 511) ? 1022 - r : r);
                int lrh = r - (oy - 6);
                lrh = min(max(lrh, 0), HBH - 1);
                s += gk[k] * B[lrh * S + lc];
            }
            A[lr * S + lc] = s;
        }
        __syncthreads();

        for (int i = tid; i < MH * MW; i += NT) {
            int lr = i / MW, lc = i - lr * MW;
            int gy = oy - 3 + lr, gx = ox - 3 + lc;
            float m = 0.f;
            int ax = 0;
            if ((unsigned)gy < 512u && (unsigned)gx < 512u) {
                int cym = min(max(gy - 1, 0), 511) - (oy - 4);
                int cy0 = gy - (oy - 4);
                int cyp = min(max(gy + 1, 0), 511) - (oy - 4);
                int cxm = min(max(gx - 1, 0), 511) - (ox - 4);
                int cx0 = gx - (ox - 4);
                int cxp = min(max(gx + 1, 0), 511) - (ox - 4);
                float bmm = A[cym * S + cxm], bm0 = A[cym * S + cx0], bmp = A[cym * S + cxp];
                float b0m = A[cy0 * S + cxm],                         b0p = A[cy0 * S + cxp];
                float bpm = A[cyp * S + cxm], bp0 = A[cyp * S + cx0], bpp = A[cyp * S + cxp];
                float sx = 0.125f * (bmp - bmm) + 0.25f * (b0p - b0m) + 0.125f * (bpp - bpm);
                float sy = 0.125f * (bpm - bmm) + 0.25f * (bp0 - bm0) + 0.125f * (bpp - bmp);
                m = sqrtf(sx * sx + sy * sy + 1e-6f);
                float adx = fabsf(sx), ady = fabsf(sy);
                if (ady <= adx * t1)       ax = 0;
                else if (ady >= adx * t2)  ax = 2;
                else                       ax = ((sx > 0.f) == (sy > 0.f)) ? 1 : 3;
            }
            B[lr * S + lc] = m;
            C[lr * S + lc] = (unsigned char)ax;
        }
        __syncthreads();

        for (int i = tid; i < NH * NW; i += NT) {
            int lr = i / NW, lc = i - lr * NW;
            int gy = oy - 2 + lr, gx = ox - 2 + lc;
            float v = 0.f;
            if ((unsigned)gy < 512u && (unsigned)gx < 512u) {
                int mi = (lr + 1) * S + (lc + 1);
                float m = B[mi];
                int ax = C[mi];
                int dy = (ax == 0) ? 0 : 1;
                int dx = (ax == 2) ? 0 : ((ax == 3) ? -1 : 1);
                float n1 = B[mi + dy * S + dx];
                float n2 = B[mi - dy * S - dx];
                v = (m > n1 && m > n2) ? m : 0.f;
            }
            A[lr * S + lc] = v;
        }
        __syncthreads();

        for (int i = tid; i < RH * RW; i += NT) {
            int lr = i / RW, lc = i - lr * RW;
            float v = A[(lr + 0) * S + lc];
            v = fmaxf(v, A[(lr + 1) * S + lc]);
            v = fmaxf(v, A[(lr + 2) * S + lc]);
            v = fmaxf(v, A[(lr + 3) * S + lc]);
            v = fmaxf(v, A[(lr + 4) * S + lc]);
            B[lr * S + lc] = v;
        }
        __syncthreads();

        for (int i = tid; i < TH * TW; i += NT) {
            int lr = i >> 6, lc = i & 63;
            const float* row = &B[lr * S + lc];
            float v = fmaxf(fmaxf(fmaxf(row[0], row[1]), fmaxf(row[2], row[3])), row[4]);
            out[((size_t)n * 512 + (oy + lr)) * 512 + (ox + lc)] = v;
        }
    }
}

extern "C" void kernel_launch(void* const* d_in, const int* in_sizes, int n_in,
                              void* d_out, int out_size)
{
    const float* x = (const float*)d_in[0];
    float* out = (float*)d_out;
    dim3 grid(512 / TW, 512 / TH, 32);
    canny_edge_kernel<<<grid, NT>>>(x, out);
}

// round 5
// speedup vs baseline: 1.2937x; 1.2937x over previous
#include <cuda_runtime.h>

#define TW 64
#define TH 32
#define NT 256
#define S  80   // unified smem row stride (floats)

#define GW 76   /* gray  cols, base ox-6 */
#define GH 44   /* gray  rows, base oy-6 */
#define HBW 72  /* hblur cols, base ox-4 (rows base oy-6) */
#define HBH 44
#define BW 72   /* blur cols, base ox-4 */
#define BH 40   /* blur rows, base oy-4 */
#define MW 70   /* mag  cols, base ox-3 */
#define MH 38   /* mag  rows, base oy-3 */
#define NW 68   /* nms  cols, base ox-2 */
#define NH 36   /* nms  rows, base oy-2 */
#define RW 68   /* colmax cols, base ox-2 */

#define LD2(p)      (*(const float2*)(p))
#define ST2(p, v)   (*(float2*)(p) = (v))

__device__ __forceinline__ int reflect2i(int c) {
    return (c < 0) ? -c : ((c > 511) ? 1022 - c : c);
}

__global__ __launch_bounds__(NT) void canny_edge_kernel(
    const float* __restrict__ x, float* __restrict__ out)
{
    __shared__ __align__(16) float A[GH * S];          // gray -> blur -> nms
    __shared__ __align__(16) float B[GH * S];          // hblur -> magsq -> colmax
    __shared__ __align__(4)  unsigned char C[MH * S];  // NMS neighbor offset byte

    const int tid = threadIdx.x;
    const int tx2 = tid & 31;   // column-pair index
    const int ty8 = tid >> 5;   // 0..7
    const int ox = blockIdx.x * TW;
    const int oy = blockIdx.y * TH;
    const int n  = blockIdx.z;

    const float gk0 = 0.054488685f;
    const float gk1 = 0.244201342f;
    const float gk2 = 0.402619947f;

    const float* c0 = x + ((size_t)n * 3 + 0) * 512 * 512;
    const float* c1 = x + ((size_t)n * 3 + 1) * 512 * 512;
    const float* c2 = x + ((size_t)n * 3 + 2) * 512 * 512;

    const bool interior = (ox >= 6) && (ox + TW + 6 <= 512) &&
                          (oy >= 6) && (oy + TH + 6 <= 512);

    const float t1 = 0.41421356237f;  // tan(22.5 deg)
    const float t2 = 2.41421356237f;  // tan(67.5 deg)

    // ---- Stage 1: grayscale into A (reflect-mapped for boundary blocks) ----
    if (interior) {
        const int gbase = (oy - 6) * 512 + (ox - 6);
        for (int lr = ty8; lr < GH; lr += 8) {
            const int rowg = gbase + lr * 512;
            #pragma unroll 2
            for (int pass = 0; pass < 2; pass++) {
                if (pass == 1 && tx2 >= (GW / 2 - 32)) break;
                int p = tx2 + pass * 32;
                float2 a0 = LD2(c0 + rowg + 2 * p);
                float2 a1 = LD2(c1 + rowg + 2 * p);
                float2 a2 = LD2(c2 + rowg + 2 * p);
                float2 g;
                g.x = 0.299f * a2.x + 0.587f * a1.x + 0.114f * a0.x;
                g.y = 0.299f * a2.y + 0.587f * a1.y + 0.114f * a0.y;
                ST2(&A[lr * S + 2 * p], g);
            }
        }
    } else {
        // Reflect-extended gray: symmetric Gaussian => uniform VALID blur of the
        // reflected signal equals reference's reflect-padded blur at all
        // in-image coords (the only ones Sobel later reads, after clamping).
        #pragma unroll 2
        for (int pass = 0; pass < 2; pass++) {
            if (pass == 1 && tx2 >= (GW / 2 - 32)) break;
            int p = tx2 + pass * 32;
            const int gxa = reflect2i(ox - 6 + 2 * p);
            const int gxb = reflect2i(ox - 6 + 2 * p + 1);
            for (int lr = ty8; lr < GH; lr += 8) {
                int rb = reflect2i(oy - 6 + lr) * 512;
                float2 g;
                g.x = 0.299f * c2[rb + gxa] + 0.587f * c1[rb + gxa] + 0.114f * c0[rb + gxa];
                g.y = 0.299f * c2[rb + gxb] + 0.587f * c1[rb + gxb] + 0.114f * c0[rb + gxb];
                ST2(&A[lr * S + 2 * p], g);
            }
        }
    }
    __syncthreads();

    // ---- Stage 2: horizontal blur -> B (uniform) ----
    for (int lr = ty8; lr < HBH; lr += 8) {
        const float* a = &A[lr * S];
        #pragma unroll 2
        for (int pass = 0; pass < 2; pass++) {
            if (pass == 1 && tx2 >= (HBW / 2 - 32)) break;
            int p = tx2 + pass * 32;
            float2 u = LD2(a + 2 * p);
            float2 v = LD2(a + 2 * p + 2);
            float2 w = LD2(a + 2 * p + 4);
            float2 o;
            o.x = gk0 * (u.x + w.x) + gk1 * (u.y + v.y) + gk2 * v.x;
            o.y = gk0 * (u.y + w.y) + gk1 * (v.x + w.x) + gk2 * v.y;
            ST2(&B[lr * S + 2 * p], o);
        }
    }
    __syncthreads();

    // ---- Stage 3: vertical blur -> A (uniform, rolling) ----
    {
        const int r0 = ty8 * 5;  // 8 chunks x 5 = 40 rows
        #pragma unroll 2
        for (int pass = 0; pass < 2; pass++) {
            if (pass == 1 && tx2 >= (BW / 2 - 32)) break;
            int c = 2 * (tx2 + pass * 32);
            float2 w0 = LD2(&B[(r0 + 0) * S + c]);
            float2 w1 = LD2(&B[(r0 + 1) * S + c]);
            float2 w2 = LD2(&B[(r0 + 2) * S + c]);
            float2 w3 = LD2(&B[(r0 + 3) * S + c]);
            #pragma unroll
            for (int j = 0; j < 5; j++) {
                float2 w4 = LD2(&B[(r0 + j + 4) * S + c]);
                float2 o;
                o.x = gk0 * (w0.x + w4.x) + gk1 * (w1.x + w3.x) + gk2 * w2.x;
                o.y = gk0 * (w0.y + w4.y) + gk1 * (w1.y + w3.y) + gk2 * w2.y;
                ST2(&A[(r0 + j) * S + c], o);
                w0 = w1; w1 = w2; w2 = w3; w3 = w4;
            }
        }
    }
    __syncthreads();

    // ---- Stage 4: Sobel -> squared magnitude in B, NMS offset byte in C ----
    if (interior) {
        const int r0 = ty8 * 5;
        const int cnt = min(5, MH - r0);
        #pragma unroll 2
        for (int pass = 0; pass < 2; pass++) {
            if (pass == 1 && tx2 >= 3) break;  // 35 pairs
            int c = 2 * (tx2 + pass * 32);
            float2 a0 = LD2(&A[(r0 + 0) * S + c]);
            float2 b0 = LD2(&A[(r0 + 0) * S + c + 2]);
            float2 a1 = LD2(&A[(r0 + 1) * S + c]);
            float2 b1 = LD2(&A[(r0 + 1) * S + c + 2]);
            for (int j = 0; j < cnt; j++) {
                float2 a2 = LD2(&A[(r0 + j + 2) * S + c]);
                float2 b2 = LD2(&A[(r0 + j + 2) * S + c + 2]);
                float sx0 = 0.125f * (b0.x - a0.x) + 0.25f * (b1.x - a1.x) + 0.125f * (b2.x - a2.x);
                float sy0 = 0.125f * (a2.x - a0.x) + 0.25f * (a2.y - a0.y) + 0.125f * (b2.x - b0.x);
                float sx1 = 0.125f * (b0.y - a0.y) + 0.25f * (b1.y - a1.y) + 0.125f * (b2.y - a2.y);
                float sy1 = 0.125f * (a2.y - a0.y) + 0.25f * (b2.x - b0.x) + 0.125f * (b2.y - b0.y);
                float2 m;
                m.x = sx0 * sx0 + sy0 * sy0 + 1e-6f;
                m.y = sx1 * sx1 + sy1 * sy1 + 1e-6f;
                float adx0 = fabsf(sx0), ady0 = fabsf(sy0);
                float adx1 = fabsf(sx1), ady1 = fabsf(sy1);
                int o0, o1;
                if (ady0 <= adx0 * t1)      o0 = 1;
                else if (ady0 >= adx0 * t2) o0 = S;
                else                        o0 = ((sx0 > 0.f) == (sy0 > 0.f)) ? S + 1 : S - 1;
                if (ady1 <= adx1 * t1)      o1 = 1;
                else if (ady1 >= adx1 * t2) o1 = S;
                else                        o1 = ((sx1 > 0.f) == (sy1 > 0.f)) ? S + 1 : S - 1;
                ST2(&B[(r0 + j) * S + c], m);
                uchar2 op; op.x = (unsigned char)o0; op.y = (unsigned char)o1;
                *(uchar2*)&C[(r0 + j) * S + c] = op;
                a0 = a1; b0 = b1;
                a1 = a2; b1 = b2;
            }
        }
    } else {
        #pragma unroll 2
        for (int pass = 0; pass < 2; pass++) {
            if (pass == 1 && tx2 >= 3) break;  // 35 pairs
            int p = tx2 + pass * 32;
            #pragma unroll
            for (int sub = 0; sub < 2; sub++) {
                int lc = 2 * p + sub;
                int gx = ox - 3 + lc;
                bool cv = (unsigned)gx < 512u;
                int cxm = min(max(gx - 1, 0), 511) - (ox - 4);
                int cx0 = min(max(gx,     0), 511) - (ox - 4);
                int cxp = min(max(gx + 1, 0), 511) - (ox - 4);
                for (int lr = ty8; lr < MH; lr += 8) {
                    int gy = oy - 3 + lr;
                    float m = 0.f;
                    int off = 1;
                    if (cv && (unsigned)gy < 512u) {
                        int cym = min(max(gy - 1, 0), 511) - (oy - 4);
                        int cy0 = gy - (oy - 4);
                        int cyp = min(max(gy + 1, 0), 511) - (oy - 4);
                        float bmm = A[cym * S + cxm], bm0 = A[cym * S + cx0], bmp = A[cym * S + cxp];
                        float b0m = A[cy0 * S + cxm],                         b0p = A[cy0 * S + cxp];
                        float bpm = A[cyp * S + cxm], bp0 = A[cyp * S + cx0], bpp = A[cyp * S + cxp];
                        float sx = 0.125f * (bmp - bmm) + 0.25f * (b0p - b0m) + 0.125f * (bpp - bpm);
                        float sy = 0.125f * (bpm - bmm) + 0.25f * (bp0 - bm0) + 0.125f * (bpp - bmp);
                        m = sx * sx + sy * sy + 1e-6f;
                        float adx = fabsf(sx), ady = fabsf(sy);
                        if (ady <= adx * t1)       off = 1;
                        else if (ady >= adx * t2)  off = S;
                        else                       off = ((sx > 0.f) == (sy > 0.f)) ? S + 1 : S - 1;
                    }
                    B[lr * S + lc] = m;
                    C[lr * S + lc] = (unsigned char)off;
                }
            }
        }
    }
    __syncthreads();

    // ---- Stage 5: NMS -> A (uniform: out-of-image magsq==0 self-suppresses) ----
    for (int lr = ty8; lr < NH; lr += 8) {
        #pragma unroll 2
        for (int pass = 0; pass < 2; pass++) {
            if (pass == 1 && tx2 >= 2) break;  // 34 pairs
            int lc = 2 * (tx2 + pass * 32);
            int mi = (lr + 1) * S + lc + 1;
            float m0 = B[mi], m1 = B[mi + 1];
            int o0 = C[mi], o1 = C[mi + 1];
            float p0 = B[mi + o0], q0 = B[mi - o0];
            float p1 = B[mi + 1 + o1], q1 = B[mi + 1 - o1];
            float2 o;
            o.x = (m0 > p0 && m0 > q0) ? m0 : 0.f;
            o.y = (m1 > p1 && m1 > q1) ? m1 : 0.f;
            ST2(&A[lr * S + lc], o);
        }
    }
    __syncthreads();

    // ---- Stage 6: vertical 5-max -> B (uniform, rolling) ----
    {
        const int r0 = ty8 * 4;  // 8 chunks x 4 = 32 rows
        #pragma unroll 2
        for (int pass = 0; pass < 2; pass++) {
            if (pass == 1 && tx2 >= 2) break;  // 34 pairs
            int c = 2 * (tx2 + pass * 32);
            float2 w0 = LD2(&A[(r0 + 0) * S + c]);
            float2 w1 = LD2(&A[(r0 + 1) * S + c]);
            float2 w2 = LD2(&A[(r0 + 2) * S + c]);
            float2 w3 = LD2(&A[(r0 + 3) * S + c]);
            #pragma unroll
            for (int j = 0; j < 4; j++) {
                float2 w4 = LD2(&A[(r0 + j + 4) * S + c]);
                float2 o;
                o.x = fmaxf(fmaxf(fmaxf(w0.x, w1.x), fmaxf(w2.x, w3.x)), w4.x);
                o.y = fmaxf(fmaxf(fmaxf(w0.y, w1.y), fmaxf(w2.y, w3.y)), w4.y);
                ST2(&B[(r0 + j) * S + c], o);
                w0 = w1; w1 = w2; w2 = w3; w3 = w4;
            }
        }
    }
    __syncthreads();

    // ---- Stage 7: horizontal 5-max + final sqrt, vectorized store ----
    for (int lr = ty8; lr < TH; lr += 8) {
        int c = 2 * tx2;
        float2 a = LD2(&B[lr * S + c]);
        float2 b = LD2(&B[lr * S + c + 2]);
        float2 d = LD2(&B[lr * S + c + 4]);
        float2 o;
        o.x = sqrtf(fmaxf(fmaxf(fmaxf(a.x, a.y), fmaxf(b.x, b.y)), d.x));
        o.y = sqrtf(fmaxf(fmaxf(fmaxf(a.y, b.x), fmaxf(b.y, d.x)), d.y));
        ST2(&out[((size_t)n * 512 + (oy + lr)) * 512 + (ox + c)], o);
    }
}

extern "C" void kernel_launch(void* const* d_in, const int* in_sizes, int n_in,
                              void* d_out, int out_size)
{
    const float* x = (const float*)d_in[0];
    float* out = (float*)d_out;
    dim3 grid(512 / TW, 512 / TH, 32);
    canny_edge_kernel<<<grid, NT>>>(x, out);
}